// round 5
// baseline (speedup 1.0000x reference)
#include <cuda_runtime.h>

#define B_   256
#define TIN  49
#define TOUT 25
#define NB   24
#define H    128
#define G5   640   // 5*H
#define OSTRIDE (TOUT*NB*H)

// ---------------- scratch (static device globals; no allocations) ----------------
__device__ float g_row_h0[NB*B_*H];
__device__ float g_row_h1[NB*B_*H];
__device__ float g_row_c [NB*B_*H];
__device__ float g_col_h [B_*H];
__device__ float g_col_c [B_*H];
__device__ float g_xu0  [TOUT*NB*B_*G5];     // p @ U[0] + b[0]
__device__ float g_h0   [TOUT*NB*B_*H];
__device__ float g_c0   [TOUT*NB*B_*H];
__device__ float g_z    [48*B_*G5];          // per-step z scratch (48 cell slots)

typedef unsigned long long u64;

__device__ __forceinline__ u64 pack2(float x, float y){
    u64 r; asm("mov.b64 %0, {%1,%2};" : "=l"(r) : "f"(x), "f"(y)); return r;
}
__device__ __forceinline__ void unpack2(u64 v, float& x, float& y){
    asm("mov.b64 {%0,%1}, %2;" : "=f"(x), "=f"(y) : "l"(v));
}
__device__ __forceinline__ u64 ffma2(u64 a, u64 b, u64 c){
    u64 d; asm("fma.rn.f32x2 %0, %1, %2, %3;" : "=l"(d) : "l"(a), "l"(b), "l"(c)); return d;
}

// ---------------- phase 0: boundary reductions ----------------
__global__ void rows_kernel(const float* __restrict__ hid,
                            const float* __restrict__ cel,
                            const float* __restrict__ gts)
{
    int gid = blockIdx.x*256 + threadIdx.x;        // over NB*B*H
    int j = gid / (B_*H);
    int rem = gid - j*(B_*H);
    int b = rem >> 7, h = rem & 127;
    const float* ph = hid + (b*TIN*NB + j)*H + h;
    const float* pc = cel + (b*TIN*NB + j)*H + h;
    float sh = 0.f, sc = 0.f;
    for (int t = 0; t < TIN; ++t) { sh += ph[t*NB*H]; sc += pc[t*NB*H]; }
    int o = (j*B_ + b)*H + h;
    g_row_h0[o] = sh * (1.0f/TIN);
    g_row_h1[o] = (gts[(b*NB + j)*H + h] + sh) * (1.0f/(TIN+1));
    g_row_c [o] = sc * (1.0f/TIN);
}

__global__ void cols_kernel()
{
    int gid = blockIdx.x*256 + threadIdx.x;        // over B*H
    float sh = 0.f, sc = 0.f;
#pragma unroll
    for (int j = 0; j < NB; ++j) {
        sh += g_row_h0[j*B_*H + gid];
        sc += g_row_c [j*B_*H + gid];
    }
    g_col_h[gid] = sh * (1.0f/NB);
    g_col_c[gid] = sc * (1.0f/NB);
}

// ---------------- fp32 GEMM core (FFMA2), 64x128 tile, BK=16, 256 thr ----------------
struct Src { const float* A; int lda; const float* W; };

__device__ __forceinline__ void gemm_tile64(const Src* src, int ns, float* Cbase,
                                            const float* bias)
{
    __shared__ float sA[16][64];
    __shared__ float sB[16][128];

    const int tid = threadIdx.x;
    const int m0 = (blockIdx.x & 3) * 64;      // 4 m-tiles
    const int n0 = (blockIdx.x >> 2) * 128;    // 5 n-tiles

    const int a_m = tid >> 2;            // 0..63
    const int a_k = (tid & 3) * 4;       // 0,4,8,12
    const int b_k = tid >> 4;            // 0..15
    const int b_n = (tid & 15) * 8;      // 0..120

    const int mreg = (tid >> 4) * 4;     // 0..60
    const int nreg = (tid & 15) * 8;     // 0..120

    u64 acc[4][4];
#pragma unroll
    for (int i = 0; i < 4; ++i)
#pragma unroll
        for (int jj = 0; jj < 4; ++jj) acc[i][jj] = 0ull;

    const int total = ns * 8;            // 8 chunks of BK=16 per 128-K source
    float4 pa, pb0, pb1;
    {
        const float* Ag = src[0].A + (m0 + a_m)*src[0].lda + a_k;
        pa = *(const float4*)Ag;
        const float* Bg = src[0].W + b_k*G5 + n0 + b_n;
        pb0 = *(const float4*)Bg;  pb1 = *(const float4*)(Bg + 4);
    }
    for (int c = 0; c < total; ++c) {
#pragma unroll
        for (int i = 0; i < 4; ++i) sA[a_k + i][a_m] = ((float*)&pa)[i];
        *(float4*)&sB[b_k][b_n]     = pb0;
        *(float4*)&sB[b_k][b_n + 4] = pb1;
        __syncthreads();
        if (c + 1 < total) {
            const int cn = c + 1;
            const Src s = src[cn >> 3];
            const int kk = (cn & 7) * 16;
            const float* Ag = s.A + (m0 + a_m)*s.lda + kk + a_k;
            pa = *(const float4*)Ag;
            const float* Bg = s.W + (kk + b_k)*G5 + n0 + b_n;
            pb0 = *(const float4*)Bg;  pb1 = *(const float4*)(Bg + 4);
        }
#pragma unroll
        for (int k = 0; k < 16; ++k) {
            float4 a = *(const float4*)&sA[k][mreg];
            ulonglong2 q0 = *(const ulonglong2*)&sB[k][nreg];
            ulonglong2 q1 = *(const ulonglong2*)&sB[k][nreg + 4];
            float av[4] = {a.x, a.y, a.z, a.w};
#pragma unroll
            for (int i = 0; i < 4; ++i) {
                u64 ad = pack2(av[i], av[i]);
                acc[i][0] = ffma2(ad, q0.x, acc[i][0]);
                acc[i][1] = ffma2(ad, q0.y, acc[i][1]);
                acc[i][2] = ffma2(ad, q1.x, acc[i][2]);
                acc[i][3] = ffma2(ad, q1.y, acc[i][3]);
            }
        }
        __syncthreads();
    }
#pragma unroll
    for (int i = 0; i < 4; ++i) {
        float* Crow = Cbase + (m0 + mreg + i)*G5 + n0 + nreg;
#pragma unroll
        for (int jj = 0; jj < 4; ++jj) {
            float x, y; unpack2(acc[i][jj], x, y);
            if (bias) { x += bias[n0 + nreg + 2*jj]; y += bias[n0 + nreg + 2*jj + 1]; }
            float2 v; v.x = x; v.y = y;
            *(float2*)(Crow + 2*jj) = v;
        }
    }
}

// ---------------- phase 1: xU0 = p @ U[0] + b[0] ----------------
__global__ __launch_bounds__(256, 3) void gemm_xu0_kernel(const float* __restrict__ p,
                                                          const float* __restrict__ U,
                                                          const float* __restrict__ bvec)
{
    int cell = blockIdx.y;
    int t = cell / NB, j = cell - t*NB;
    Src s[1];
    s[0].A = p + (t*NB + j)*H;  s[0].lda = OSTRIDE;  s[0].W = U + j*H*G5;
    gemm_tile64(s, 1, g_xu0 + (long)cell*B_*G5, bvec + j*G5);
}

// ---------------- phase 2: wavefront steps (d = t + j (+1 for rec1)) ----------------
struct StepList { int n; int cells[64]; };

__global__ __launch_bounds__(256, 3) void gemm_step_kernel(StepList sl,
                                                           const float* __restrict__ U,
                                                           const float* __restrict__ Wt,
                                                           const float* __restrict__ Ws,
                                                           const float* __restrict__ bvec,
                                                           const float* __restrict__ outH)
{
    int code = sl.cells[blockIdx.y];
    int r = code >> 16, t = (code >> 8) & 255, j = code & 255;
    Src s[3]; int ns;
    const float* bias = nullptr;
    if (r == 0) {
        ns = 2;
        s[0].A = (t == 0) ? g_row_h0 + j*B_*H : g_h0 + ((t-1)*NB + j)*B_*H;
        s[0].lda = H;  s[0].W = Wt + j*H*G5;
        s[1].A = (j == 0) ? g_col_h : g_h0 + (t*NB + (j-1))*B_*H;
        s[1].lda = H;  s[1].W = Ws + j*H*G5;
    } else {
        ns = 3;
        s[0].A = g_h0 + (t*NB + j)*B_*H;  s[0].lda = H;  s[0].W = U + (NB + j)*H*G5;
        if (t == 0) { s[1].A = g_row_h1 + j*B_*H;          s[1].lda = H; }
        else        { s[1].A = outH + ((t-1)*NB + j)*H;    s[1].lda = OSTRIDE; }
        s[1].W = Wt + (NB + j)*H*G5;
        if (j == 0) { s[2].A = g_col_h;                    s[2].lda = H; }
        else        { s[2].A = outH + (t*NB + (j-1))*H;    s[2].lda = OSTRIDE; }
        s[2].W = Ws + (NB + j)*H*G5;
        bias = bvec + (NB + j)*G5;
    }
    gemm_tile64(s, ns, g_z + (long)blockIdx.y*B_*G5, bias);
}

__device__ __forceinline__ float sigf(float x){ return 1.0f/(1.0f + __expf(-x)); }
__device__ __forceinline__ float tanhfast(float x){ return 2.0f*sigf(2.0f*x) - 1.0f; }

__global__ __launch_bounds__(256) void ew_step_kernel(StepList sl,
                                                      float* __restrict__ outH)
{
    int code = sl.cells[blockIdx.y];
    int r = code >> 16, t = (code >> 8) & 255, j = code & 255;
    int e = blockIdx.x*256 + threadIdx.x;      // 0..B*H-1
    int m = e >> 7, h = e & 127;
    const float* zb = g_z + (long)blockIdx.y*B_*G5 + m*G5 + h;
    float z0 = zb[0], z1 = zb[128], z2 = zb[256], z3 = zb[384], z4 = zb[512];
    float ct, cs;
    float* outC = outH + (long)B_*TOUT*NB*H;
    if (r == 0) {
        const float* xb = g_xu0 + ((long)(t*NB + j)*B_ + m)*G5 + h;
        z0 += xb[0]; z1 += xb[128]; z2 += xb[256]; z3 += xb[384]; z4 += xb[512];
        ct = (t == 0) ? g_row_c[(j*B_ + m)*H + h]
                      : g_c0[(((t-1)*NB + j)*B_ + m)*H + h];
        cs = (j == 0) ? g_col_c[m*H + h]
                      : g_c0[((t*NB + (j-1))*B_ + m)*H + h];
    } else {
        ct = (t == 0) ? g_row_c[(j*B_ + m)*H + h]
                      : outC[((m*TOUT + (t-1))*NB + j)*H + h];
        cs = (j == 0) ? g_col_c[m*H + h]
                      : outC[((m*TOUT + t)*NB + (j-1))*H + h];
    }
    // gate order: i, f_s, f_t, o, g
    float in_ = sigf(z0), fs = sigf(z1), ft = sigf(z2), o = sigf(z3), g = tanhfast(z4);
    float c  = in_*g + ft*ct + fs*cs;
    float hv = o * tanhfast(c);
    if (r == 0) {
        int idx = ((t*NB + j)*B_ + m)*H + h;
        g_h0[idx] = hv;  g_c0[idx] = c;
    } else {
        int idx = ((m*TOUT + t)*NB + j)*H + h;
        outH[idx] = hv;  outC[idx] = c;
    }
}

// ---------------- launch ----------------
extern "C" void kernel_launch(void* const* d_in, const int* in_sizes, int n_in,
                              void* d_out, int out_size)
{
    const float* hid = (const float*)d_in[0];
    const float* cel = (const float*)d_in[1];
    const float* gts = (const float*)d_in[2];
    const float* p   = (const float*)d_in[3];
    const float* U   = (const float*)d_in[4];
    const float* Wt  = (const float*)d_in[5];
    const float* Ws  = (const float*)d_in[6];
    const float* bv  = (const float*)d_in[7];
    float* outH = (float*)d_out;

    rows_kernel<<<NB*B_*H/256, 256>>>(hid, cel, gts);
    cols_kernel<<<B_*H/256, 256>>>();
    gemm_xu0_kernel<<<dim3(20, TOUT*NB), 256>>>(p, U, bv);

    // wavefront: rec0 at d = t+j, rec1 at d = t+j+1, d in [0, 48]
    for (int d = 0; d <= (TOUT-1) + (NB-1) + 1; ++d) {
        StepList sl; sl.n = 0;
        for (int t = 0; t < TOUT; ++t) {               // rec 0: t + j = d
            int j = d - t;
            if (j >= 0 && j < NB) sl.cells[sl.n++] = (0 << 16) | (t << 8) | j;
        }
        for (int t = 0; t < TOUT; ++t) {               // rec 1: t + j = d - 1
            int j = d - 1 - t;
            if (j >= 0 && j < NB) sl.cells[sl.n++] = (1 << 16) | (t << 8) | j;
        }
        if (!sl.n) continue;
        gemm_step_kernel<<<dim3(20, sl.n), 256>>>(sl, U, Wt, Ws, bv, outH);
        ew_step_kernel<<<dim3(B_*H/256, sl.n), 256>>>(sl, outH);
    }
}

// round 6
// speedup vs baseline: 1.0827x; 1.0827x over previous
#include <cuda_runtime.h>

#define B_   256
#define TIN  49
#define TOUT 25
#define NB   24
#define H    128
#define G5   640   // 5*H
#define OSTRIDE (TOUT*NB*H)

// ---------------- scratch (static device globals; no allocations) ----------------
__device__ float g_row_h0[NB*B_*H];
__device__ float g_row_h1[NB*B_*H];
__device__ float g_row_c [NB*B_*H];
__device__ float g_col_h [B_*H];
__device__ float g_col_c [B_*H];
__device__ float g_xu0  [TOUT*NB*B_*G5];       // p @ U[0] + b[0]
__device__ float g_h0   [TOUT*NB*B_*H];
__device__ float g_c0   [TOUT*NB*B_*H];
__device__ float g_z    [48*3*B_*G5];          // per-step z: 48 cells x 3 source slices

typedef unsigned long long u64;

__device__ __forceinline__ u64 pack2(float x, float y){
    u64 r; asm("mov.b64 %0, {%1,%2};" : "=l"(r) : "f"(x), "f"(y)); return r;
}
__device__ __forceinline__ void unpack2(u64 v, float& x, float& y){
    asm("mov.b64 {%0,%1}, %2;" : "=f"(x), "=f"(y) : "l"(v));
}
__device__ __forceinline__ u64 ffma2(u64 a, u64 b, u64 c){
    u64 d; asm("fma.rn.f32x2 %0, %1, %2, %3;" : "=l"(d) : "l"(a), "l"(b), "l"(c)); return d;
}

// ---------------- phase 0: boundary reductions ----------------
__global__ void rows_kernel(const float* __restrict__ hid,
                            const float* __restrict__ cel,
                            const float* __restrict__ gts)
{
    int gid = blockIdx.x*256 + threadIdx.x;        // over NB*B*H
    int j = gid / (B_*H);
    int rem = gid - j*(B_*H);
    int b = rem >> 7, h = rem & 127;
    const float* ph = hid + (b*TIN*NB + j)*H + h;
    const float* pc = cel + (b*TIN*NB + j)*H + h;
    float sh = 0.f, sc = 0.f;
    for (int t = 0; t < TIN; ++t) { sh += ph[t*NB*H]; sc += pc[t*NB*H]; }
    int o = (j*B_ + b)*H + h;
    g_row_h0[o] = sh * (1.0f/TIN);
    g_row_h1[o] = (gts[(b*NB + j)*H + h] + sh) * (1.0f/(TIN+1));
    g_row_c [o] = sc * (1.0f/TIN);
}

__global__ void cols_kernel()
{
    int gid = blockIdx.x*256 + threadIdx.x;        // over B*H
    float sh = 0.f, sc = 0.f;
#pragma unroll
    for (int j = 0; j < NB; ++j) {
        sh += g_row_h0[j*B_*H + gid];
        sc += g_row_c [j*B_*H + gid];
    }
    g_col_h[gid] = sh * (1.0f/NB);
    g_col_c[gid] = sc * (1.0f/NB);
}

// ------- fp32 GEMM core: 64x128 tile, single K=128 source, double-buffered -------
__device__ __forceinline__ void gemm_src(const float* __restrict__ A, int lda,
                                         const float* __restrict__ W,
                                         float* __restrict__ Cbase,
                                         const float* __restrict__ bias)
{
    __shared__ float sA[2][16][64];
    __shared__ float sB[2][16][128];

    const int tid = threadIdx.x;
    const int m0 = (blockIdx.x & 3) * 64;      // 4 m-tiles of 64
    const int n0 = (blockIdx.x >> 2) * 128;    // 5 n-tiles of 128

    const int a_m = tid >> 2;            // 0..63
    const int a_k = (tid & 3) * 4;       // 0,4,8,12
    const int b_k = tid >> 4;            // 0..15
    const int b_n = (tid & 15) * 8;      // 0..120

    const int mreg = (tid >> 4) * 4;     // 0..60
    const int nreg = (tid & 15) * 8;     // 0..120

    const float* Ag = A + (m0 + a_m)*lda + a_k;
    const float* Bg = W + b_k*G5 + n0 + b_n;

    u64 acc[4][4];
#pragma unroll
    for (int i = 0; i < 4; ++i)
#pragma unroll
        for (int jj = 0; jj < 4; ++jj) acc[i][jj] = 0ull;

    float4 ra, rb0, rb1;
    // prologue: chunk 0 -> buf0, prefetch chunk 1
    ra  = *(const float4*)(Ag);
    rb0 = *(const float4*)(Bg);
    rb1 = *(const float4*)(Bg + 4);
#pragma unroll
    for (int i = 0; i < 4; ++i) sA[0][a_k + i][a_m] = ((float*)&ra)[i];
    *(float4*)&sB[0][b_k][b_n]     = rb0;
    *(float4*)&sB[0][b_k][b_n + 4] = rb1;
    ra  = *(const float4*)(Ag + 16);
    rb0 = *(const float4*)(Bg + 16*G5);
    rb1 = *(const float4*)(Bg + 16*G5 + 4);
    __syncthreads();

#pragma unroll
    for (int c = 0; c < 8; ++c) {
        const int cur = c & 1, nxt = cur ^ 1;
        if (c + 1 < 8) {                       // store prefetched chunk c+1
#pragma unroll
            for (int i = 0; i < 4; ++i) sA[nxt][a_k + i][a_m] = ((float*)&ra)[i];
            *(float4*)&sB[nxt][b_k][b_n]     = rb0;
            *(float4*)&sB[nxt][b_k][b_n + 4] = rb1;
        }
        if (c + 2 < 8) {                       // prefetch chunk c+2
            ra  = *(const float4*)(Ag + (c+2)*16);
            rb0 = *(const float4*)(Bg + (c+2)*16*G5);
            rb1 = *(const float4*)(Bg + (c+2)*16*G5 + 4);
        }
#pragma unroll
        for (int k = 0; k < 16; ++k) {
            float4 a = *(const float4*)&sA[cur][k][mreg];
            ulonglong2 q0 = *(const ulonglong2*)&sB[cur][k][nreg];
            ulonglong2 q1 = *(const ulonglong2*)&sB[cur][k][nreg + 4];
            float av[4] = {a.x, a.y, a.z, a.w};
#pragma unroll
            for (int i = 0; i < 4; ++i) {
                u64 ad = pack2(av[i], av[i]);
                acc[i][0] = ffma2(ad, q0.x, acc[i][0]);
                acc[i][1] = ffma2(ad, q0.y, acc[i][1]);
                acc[i][2] = ffma2(ad, q1.x, acc[i][2]);
                acc[i][3] = ffma2(ad, q1.y, acc[i][3]);
            }
        }
        __syncthreads();                       // one barrier per chunk
    }

#pragma unroll
    for (int i = 0; i < 4; ++i) {
        float* Crow = Cbase + (m0 + mreg + i)*G5 + n0 + nreg;
#pragma unroll
        for (int jj = 0; jj < 4; ++jj) {
            float x, y; unpack2(acc[i][jj], x, y);
            if (bias) { x += bias[n0 + nreg + 2*jj]; y += bias[n0 + nreg + 2*jj + 1]; }
            float2 v; v.x = x; v.y = y;
            *(float2*)(Crow + 2*jj) = v;
        }
    }
}

// ---------------- phase 1: xU0 = p @ U[0] + b[0] ----------------
__global__ __launch_bounds__(256, 3) void gemm_xu0_kernel(const float* __restrict__ p,
                                                          const float* __restrict__ U,
                                                          const float* __restrict__ bvec)
{
    int cell = blockIdx.y;
    int t = cell / NB, j = cell - t*NB;
    gemm_src(p + (t*NB + j)*H, OSTRIDE, U + j*H*G5,
             g_xu0 + (long)cell*B_*G5, bvec + j*G5);
}

// ---------------- phase 2: wavefront steps (d = t + j (+1 for rec1)) ----------------
struct StepList { int n; int cells[64]; };

__global__ __launch_bounds__(256, 3) void gemm_step_kernel(StepList sl,
                                                           const float* __restrict__ U,
                                                           const float* __restrict__ Wt,
                                                           const float* __restrict__ Ws,
                                                           const float* __restrict__ bvec,
                                                           const float* __restrict__ outH)
{
    int code = sl.cells[blockIdx.y];
    int r = code >> 16, t = (code >> 8) & 255, j = code & 255;
    int src = blockIdx.z;
    const float* A; int lda; const float* W; const float* bias = nullptr;
    if (r == 0) {
        if (src == 2) return;                  // rec-0 has only 2 recurrent sources
        if (src == 0) {
            A = (t == 0) ? g_row_h0 + j*B_*H : g_h0 + ((t-1)*NB + j)*B_*H;
            lda = H;  W = Wt + j*H*G5;
        } else {
            A = (j == 0) ? g_col_h : g_h0 + (t*NB + (j-1))*B_*H;
            lda = H;  W = Ws + j*H*G5;
        }
    } else {
        if (src == 0) {
            A = g_h0 + (t*NB + j)*B_*H;  lda = H;  W = U + (NB + j)*H*G5;
            bias = bvec + (NB + j)*G5;
        } else if (src == 1) {
            if (t == 0) { A = g_row_h1 + j*B_*H;        lda = H; }
            else        { A = outH + ((t-1)*NB + j)*H;  lda = OSTRIDE; }
            W = Wt + (NB + j)*H*G5;
        } else {
            if (j == 0) { A = g_col_h;                  lda = H; }
            else        { A = outH + (t*NB + (j-1))*H;  lda = OSTRIDE; }
            W = Ws + (NB + j)*H*G5;
        }
    }
    gemm_src(A, lda, W, g_z + ((long)blockIdx.y*3 + src)*B_*G5, bias);
}

__device__ __forceinline__ float sigf(float x){ return 1.0f/(1.0f + __expf(-x)); }
__device__ __forceinline__ float tanhfast(float x){ return 2.0f*sigf(2.0f*x) - 1.0f; }

__global__ __launch_bounds__(256) void ew_step_kernel(StepList sl,
                                                      float* __restrict__ outH)
{
    int code = sl.cells[blockIdx.y];
    int r = code >> 16, t = (code >> 8) & 255, j = code & 255;
    int e = blockIdx.x*256 + threadIdx.x;      // 0..B*H-1
    int m = e >> 7, h = e & 127;
    const float* zb = g_z + (long)blockIdx.y*3*B_*G5 + m*G5 + h;
    const float* z1p = zb + (long)B_*G5;
    const float* z2p = zb + (long)2*B_*G5;
    float z0 = zb[0]   + z1p[0];
    float z1 = zb[128] + z1p[128];
    float z2 = zb[256] + z1p[256];
    float z3 = zb[384] + z1p[384];
    float z4 = zb[512] + z1p[512];
    float ct, cs;
    float* outC = outH + (long)B_*TOUT*NB*H;
    if (r == 0) {
        const float* xb = g_xu0 + ((long)(t*NB + j)*B_ + m)*G5 + h;
        z0 += xb[0]; z1 += xb[128]; z2 += xb[256]; z3 += xb[384]; z4 += xb[512];
        ct = (t == 0) ? g_row_c[(j*B_ + m)*H + h]
                      : g_c0[(((t-1)*NB + j)*B_ + m)*H + h];
        cs = (j == 0) ? g_col_c[m*H + h]
                      : g_c0[((t*NB + (j-1))*B_ + m)*H + h];
    } else {
        z0 += z2p[0]; z1 += z2p[128]; z2 += z2p[256]; z3 += z2p[384]; z4 += z2p[512];
        ct = (t == 0) ? g_row_c[(j*B_ + m)*H + h]
                      : outC[((m*TOUT + (t-1))*NB + j)*H + h];
        cs = (j == 0) ? g_col_c[m*H + h]
                      : outC[((m*TOUT + t)*NB + (j-1))*H + h];
    }
    // gate order: i, f_s, f_t, o, g
    float in_ = sigf(z0), fs = sigf(z1), ft = sigf(z2), o = sigf(z3), g = tanhfast(z4);
    float c  = in_*g + ft*ct + fs*cs;
    float hv = o * tanhfast(c);
    if (r == 0) {
        int idx = ((t*NB + j)*B_ + m)*H + h;
        g_h0[idx] = hv;  g_c0[idx] = c;
    } else {
        int idx = ((m*TOUT + t)*NB + j)*H + h;
        outH[idx] = hv;  outC[idx] = c;
    }
}

// ---------------- launch ----------------
extern "C" void kernel_launch(void* const* d_in, const int* in_sizes, int n_in,
                              void* d_out, int out_size)
{
    const float* hid = (const float*)d_in[0];
    const float* cel = (const float*)d_in[1];
    const float* gts = (const float*)d_in[2];
    const float* p   = (const float*)d_in[3];
    const float* U   = (const float*)d_in[4];
    const float* Wt  = (const float*)d_in[5];
    const float* Ws  = (const float*)d_in[6];
    const float* bv  = (const float*)d_in[7];
    float* outH = (float*)d_out;

    rows_kernel<<<NB*B_*H/256, 256>>>(hid, cel, gts);
    cols_kernel<<<B_*H/256, 256>>>();
    gemm_xu0_kernel<<<dim3(20, TOUT*NB), 256>>>(p, U, bv);

    // wavefront: rec0 at d = t+j, rec1 at d = t+j+1, d in [0, 48]
    for (int d = 0; d <= (TOUT-1) + (NB-1) + 1; ++d) {
        StepList sl; sl.n = 0;
        for (int t = 0; t < TOUT; ++t) {               // rec 0: t + j = d
            int j = d - t;
            if (j >= 0 && j < NB) sl.cells[sl.n++] = (0 << 16) | (t << 8) | j;
        }
        for (int t = 0; t < TOUT; ++t) {               // rec 1: t + j = d - 1
            int j = d - 1 - t;
            if (j >= 0 && j < NB) sl.cells[sl.n++] = (1 << 16) | (t << 8) | j;
        }
        if (!sl.n) continue;
        gemm_step_kernel<<<dim3(20, sl.n, 3), 256>>>(sl, U, Wt, Ws, bv, outH);
        ew_step_kernel<<<dim3(B_*H/256, sl.n), 256>>>(sl, outH);
    }
}

// round 11
// speedup vs baseline: 1.1730x; 1.0834x over previous
#include <cuda_runtime.h>
#include <cstdint>

#define B_   256
#define TIN  49
#define TOUT 25
#define NB   24
#define H    128
#define G5   640   // 5*H
#define OSTRIDE (TOUT*NB*H)

// ---------------- scratch (static device globals; no allocations) ----------------
__device__ float g_row_h0[NB*B_*H];
__device__ float g_row_h1[NB*B_*H];
__device__ float g_row_c [NB*B_*H];
__device__ float g_col_h [B_*H];
__device__ float g_col_c [B_*H];
__device__ float g_xu0  [TOUT*NB*B_*G5];       // p @ U[0] + b[0]
__device__ float g_h0   [TOUT*NB*B_*H];
__device__ float g_c0   [TOUT*NB*B_*H];
__device__ float g_z    [48*3*B_*G5];          // per-step z: 48 cells x 3 source slices

typedef unsigned long long u64;

__device__ __forceinline__ u64 pack2(float x, float y){
    u64 r; asm("mov.b64 %0, {%1,%2};" : "=l"(r) : "f"(x), "f"(y)); return r;
}
__device__ __forceinline__ void unpack2(u64 v, float& x, float& y){
    asm("mov.b64 {%0,%1}, %2;" : "=f"(x), "=f"(y) : "l"(v));
}
__device__ __forceinline__ u64 ffma2(u64 a, u64 b, u64 c){
    u64 d; asm("fma.rn.f32x2 %0, %1, %2, %3;" : "=l"(d) : "l"(a), "l"(b), "l"(c)); return d;
}
__device__ __forceinline__ void cp16(uint32_t smem, const float* g){
    asm volatile("cp.async.cg.shared.global [%0], [%1], 16;" :: "r"(smem), "l"(g));
}
__device__ __forceinline__ void cp_commit(){ asm volatile("cp.async.commit_group;"); }
template<int N> __device__ __forceinline__ void cp_wait(){
    asm volatile("cp.async.wait_group %0;" :: "n"(N));
}

// ---------------- phase 0: boundary reductions ----------------
__global__ void rows_kernel(const float* __restrict__ hid,
                            const float* __restrict__ cel,
                            const float* __restrict__ gts)
{
    int gid = blockIdx.x*256 + threadIdx.x;        // over NB*B*H
    int j = gid / (B_*H);
    int rem = gid - j*(B_*H);
    int b = rem >> 7, h = rem & 127;
    const float* ph = hid + (b*TIN*NB + j)*H + h;
    const float* pc = cel + (b*TIN*NB + j)*H + h;
    float sh = 0.f, sc = 0.f;
    for (int t = 0; t < TIN; ++t) { sh += ph[t*NB*H]; sc += pc[t*NB*H]; }
    int o = (j*B_ + b)*H + h;
    g_row_h0[o] = sh * (1.0f/TIN);
    g_row_h1[o] = (gts[(b*NB + j)*H + h] + sh) * (1.0f/(TIN+1));
    g_row_c [o] = sc * (1.0f/TIN);
}

__global__ void cols_kernel()
{
    int gid = blockIdx.x*256 + threadIdx.x;        // over B*H
    float sh = 0.f, sc = 0.f;
#pragma unroll
    for (int j = 0; j < NB; ++j) {
        sh += g_row_h0[j*B_*H + gid];
        sc += g_row_c [j*B_*H + gid];
    }
    g_col_h[gid] = sh * (1.0f/NB);
    g_col_c[gid] = sc * (1.0f/NB);
}

// ------- fp32 GEMM core: 64x128 tile, K=128, A fully staged, B 4-stage cp.async -------
__device__ __forceinline__ void gemm_src(const float* __restrict__ A, int lda,
                                         const float* __restrict__ W,
                                         float* __restrict__ Cbase,
                                         const float* __restrict__ bias)
{
    __shared__ float sA[128][64];          // [k][m]  32 KB
    __shared__ float sB[4][8][128];        // 4-stage ring, BK=8  16 KB

    const int tid = threadIdx.x;
    const int m0 = (blockIdx.x & 3) * 64;      // 4 m-tiles of 64
    const int n0 = (blockIdx.x >> 2) * 128;    // 5 n-tiles of 128

    // A staging map: thread -> row m, k-quad
    const int am = tid >> 2;             // 0..63
    const int ak = (tid & 3) * 4;        // 0,4,8,12 (then +16*pos)
    // B cp.async map: thread -> k-row, n-quad
    const int bk = tid >> 5;             // 0..7
    const int bn = (tid & 31) * 4;       // 0..124

    const int mreg = (tid >> 4) * 4;     // 0..60
    const int nreg = (tid & 15) * 8;     // 0..120

    const float* Arow = A + (m0 + am)*lda + ak;
    const float* Bbase = W + bk*G5 + n0 + bn;
    uint32_t sb_dst = (uint32_t)__cvta_generic_to_shared(&sB[0][bk][bn]);

    // ---- prologue: issue B chunks 0..2, stage all of A ----
#pragma unroll
    for (int ch = 0; ch < 3; ++ch) {
        cp16(sb_dst + (uint32_t)(ch*8*128*4), Bbase + ch*8*G5);
        cp_commit();
    }
#pragma unroll
    for (int pos = 0; pos < 8; ++pos) {
        float4 v = *(const float4*)(Arow + pos*16);
        sA[ak + pos*16 + 0][am] = v.x;
        sA[ak + pos*16 + 1][am] = v.y;
        sA[ak + pos*16 + 2][am] = v.z;
        sA[ak + pos*16 + 3][am] = v.w;
    }

    u64 acc[4][4];
#pragma unroll
    for (int i = 0; i < 4; ++i)
#pragma unroll
        for (int jj = 0; jj < 4; ++jj) acc[i][jj] = 0ull;

    // ---- mainloop: 16 chunks of BK=8 ----
#pragma unroll
    for (int c = 0; c < 16; ++c) {
        if (c <= 13) cp_wait<2>(); else if (c == 14) cp_wait<1>(); else cp_wait<0>();
        __syncthreads();
        if (c + 3 < 16) {
            cp16(sb_dst + (uint32_t)(((c+3)&3)*8*128*4), Bbase + (c+3)*8*G5);
            cp_commit();
        }
        const int st = c & 3;
#pragma unroll
        for (int k = 0; k < 8; ++k) {
            float4 a = *(const float4*)&sA[c*8 + k][mreg];
            ulonglong2 q0 = *(const ulonglong2*)&sB[st][k][nreg];
            ulonglong2 q1 = *(const ulonglong2*)&sB[st][k][nreg + 4];
            float av[4] = {a.x, a.y, a.z, a.w};
#pragma unroll
            for (int i = 0; i < 4; ++i) {
                u64 ad = pack2(av[i], av[i]);
                acc[i][0] = ffma2(ad, q0.x, acc[i][0]);
                acc[i][1] = ffma2(ad, q0.y, acc[i][1]);
                acc[i][2] = ffma2(ad, q1.x, acc[i][2]);
                acc[i][3] = ffma2(ad, q1.y, acc[i][3]);
            }
        }
    }

#pragma unroll
    for (int i = 0; i < 4; ++i) {
        float* Crow = Cbase + (m0 + mreg + i)*G5 + n0 + nreg;
#pragma unroll
        for (int jj = 0; jj < 4; ++jj) {
            float x, y; unpack2(acc[i][jj], x, y);
            if (bias) { x += bias[n0 + nreg + 2*jj]; y += bias[n0 + nreg + 2*jj + 1]; }
            float2 v; v.x = x; v.y = y;
            *(float2*)(Crow + 2*jj) = v;
        }
    }
}

// ---------------- phase 1: xU0 = p @ U[0] + b[0] ----------------
__global__ __launch_bounds__(256, 3) void gemm_xu0_kernel(const float* __restrict__ p,
                                                          const float* __restrict__ U,
                                                          const float* __restrict__ bvec)
{
    int cell = blockIdx.y;
    int t = cell / NB, j = cell - t*NB;
    gemm_src(p + (t*NB + j)*H, OSTRIDE, U + j*H*G5,
             g_xu0 + (long)cell*B_*G5, bvec + j*G5);
}

// ---------------- phase 2: wavefront steps (d = t + j (+1 for rec1)) ----------------
struct StepList { int n; int cells[64]; };

__global__ __launch_bounds__(256, 3) void gemm_step_kernel(StepList sl,
                                                           const float* __restrict__ U,
                                                           const float* __restrict__ Wt,
                                                           const float* __restrict__ Ws,
                                                           const float* __restrict__ bvec,
                                                           const float* __restrict__ outH)
{
    int code = sl.cells[blockIdx.y];
    int r = code >> 16, t = (code >> 8) & 255, j = code & 255;
    int src = blockIdx.z;
    const float* A; int lda; const float* W; const float* bias = nullptr;
    if (r == 0) {
        if (src == 2) return;                  // rec-0 has only 2 recurrent sources
        if (src == 0) {
            A = (t == 0) ? g_row_h0 + j*B_*H : g_h0 + ((t-1)*NB + j)*B_*H;
            lda = H;  W = Wt + j*H*G5;
        } else {
            A = (j == 0) ? g_col_h : g_h0 + (t*NB + (j-1))*B_*H;
            lda = H;  W = Ws + j*H*G5;
        }
    } else {
        if (src == 0) {
            A = g_h0 + (t*NB + j)*B_*H;  lda = H;  W = U + (NB + j)*H*G5;
            bias = bvec + (NB + j)*G5;
        } else if (src == 1) {
            if (t == 0) { A = g_row_h1 + j*B_*H;        lda = H; }
            else        { A = outH + ((t-1)*NB + j)*H;  lda = OSTRIDE; }
            W = Wt + (NB + j)*H*G5;
        } else {
            if (j == 0) { A = g_col_h;                  lda = H; }
            else        { A = outH + (t*NB + (j-1))*H;  lda = OSTRIDE; }
            W = Ws + (NB + j)*H*G5;
        }
    }
    gemm_src(A, lda, W, g_z + ((long)blockIdx.y*3 + src)*B_*G5, bias);
}

__device__ __forceinline__ float sigf(float x){ return 1.0f/(1.0f + __expf(-x)); }
__device__ __forceinline__ float tanhfast(float x){ return 2.0f*sigf(2.0f*x) - 1.0f; }

__global__ __launch_bounds__(256) void ew_step_kernel(StepList sl,
                                                      float* __restrict__ outH)
{
    int code = sl.cells[blockIdx.y];
    int r = code >> 16, t = (code >> 8) & 255, j = code & 255;
    int e = blockIdx.x*256 + threadIdx.x;      // 0..B*H-1
    int m = e >> 7, h = e & 127;
    const float* zb = g_z + (long)blockIdx.y*3*B_*G5 + m*G5 + h;
    const float* z1p = zb + (long)B_*G5;
    const float* z2p = zb + (long)2*B_*G5;
    float z0 = zb[0]   + z1p[0];
    float z1 = zb[128] + z1p[128];
    float z2 = zb[256] + z1p[256];
    float z3 = zb[384] + z1p[384];
    float z4 = zb[512] + z1p[512];
    float ct, cs;
    float* outC = outH + (long)B_*TOUT*NB*H;
    if (r == 0) {
        const float* xb = g_xu0 + ((long)(t*NB + j)*B_ + m)*G5 + h;
        z0 += xb[0]; z1 += xb[128]; z2 += xb[256]; z3 += xb[384]; z4 += xb[512];
        ct = (t == 0) ? g_row_c[(j*B_ + m)*H + h]
                      : g_c0[(((t-1)*NB + j)*B_ + m)*H + h];
        cs = (j == 0) ? g_col_c[m*H + h]
                      : g_c0[((t*NB + (j-1))*B_ + m)*H + h];
    } else {
        z0 += z2p[0]; z1 += z2p[128]; z2 += z2p[256]; z3 += z2p[384]; z4 += z2p[512];
        ct = (t == 0) ? g_row_c[(j*B_ + m)*H + h]
                      : outC[((m*TOUT + (t-1))*NB + j)*H + h];
        cs = (j == 0) ? g_col_c[m*H + h]
                      : outC[((m*TOUT + t)*NB + (j-1))*H + h];
    }
    // gate order: i, f_s, f_t, o, g
    float in_ = sigf(z0), fs = sigf(z1), ft = sigf(z2), o = sigf(z3), g = tanhfast(z4);
    float c  = in_*g + ft*ct + fs*cs;
    float hv = o * tanhfast(c);
    if (r == 0) {
        int idx = ((t*NB + j)*B_ + m)*H + h;
        g_h0[idx] = hv;  g_c0[idx] = c;
    } else {
        int idx = ((m*TOUT + t)*NB + j)*H + h;
        outH[idx] = hv;  outC[idx] = c;
    }
}

// ---------------- launch ----------------
extern "C" void kernel_launch(void* const* d_in, const int* in_sizes, int n_in,
                              void* d_out, int out_size)
{
    const float* hid = (const float*)d_in[0];
    const float* cel = (const float*)d_in[1];
    const float* gts = (const float*)d_in[2];
    const float* p   = (const float*)d_in[3];
    const float* U   = (const float*)d_in[4];
    const float* Wt  = (const float*)d_in[5];
    const float* Ws  = (const float*)d_in[6];
    const float* bv  = (const float*)d_in[7];
    float* outH = (float*)d_out;

    rows_kernel<<<NB*B_*H/256, 256>>>(hid, cel, gts);
    cols_kernel<<<B_*H/256, 256>>>();
    gemm_xu0_kernel<<<dim3(20, TOUT*NB), 256>>>(p, U, bv);

    // wavefront: rec0 at d = t+j, rec1 at d = t+j+1, d in [0, 48]
    for (int d = 0; d <= (TOUT-1) + (NB-1) + 1; ++d) {
        StepList sl; sl.n = 0;
        for (int t = 0; t < TOUT; ++t) {               // rec 0: t + j = d
            int j = d - t;
            if (j >= 0 && j < NB) sl.cells[sl.n++] = (0 << 16) | (t << 8) | j;
        }
        for (int t = 0; t < TOUT; ++t) {               // rec 1: t + j = d - 1
            int j = d - 1 - t;
            if (j >= 0 && j < NB) sl.cells[sl.n++] = (1 << 16) | (t << 8) | j;
        }
        if (!sl.n) continue;
        gemm_step_kernel<<<dim3(20, sl.n, 3), 256>>>(sl, U, Wt, Ws, bv, outH);
        ew_step_kernel<<<dim3(B_*H/256, sl.n), 256>>>(sl, outH);
    }
}

// round 14
// speedup vs baseline: 2.0816x; 1.7747x over previous
#include <cuda_runtime.h>
#include <cstdint>

#define B_   256
#define TIN  49
#define TOUT 25
#define NB   24
#define H    128
#define G5   640   // 5*H
#define OSTRIDE (TOUT*NB*H)

// ---------------- scratch (static device globals; no allocations) ----------------
__device__ float g_row_h0[NB*B_*H];
__device__ float g_row_h1[NB*B_*H];
__device__ float g_row_c [NB*B_*H];
__device__ float g_col_h [B_*H];
__device__ float g_col_c [B_*H];
__device__ float g_xu0  [TOUT*NB*B_*G5];       // p @ U[0] + b[0]
__device__ float g_h0   [TOUT*NB*B_*H];
__device__ float g_c0   [TOUT*NB*B_*H];
__device__ float g_z    [48*3*B_*G5];          // per-step z: 48 cells x 3 source slices

typedef unsigned long long u64;

__device__ __forceinline__ u64 pack2(float x, float y){
    u64 r; asm("mov.b64 %0, {%1,%2};" : "=l"(r) : "f"(x), "f"(y)); return r;
}
__device__ __forceinline__ void unpack2(u64 v, float& x, float& y){
    asm("mov.b64 {%0,%1}, %2;" : "=f"(x), "=f"(y) : "l"(v));
}
__device__ __forceinline__ u64 ffma2(u64 a, u64 b, u64 c){
    u64 d; asm("fma.rn.f32x2 %0, %1, %2, %3;" : "=l"(d) : "l"(a), "l"(b), "l"(c)); return d;
}
__device__ __forceinline__ void cp16(uint32_t smem, const float* g){
    asm volatile("cp.async.cg.shared.global [%0], [%1], 16;" :: "r"(smem), "l"(g));
}
__device__ __forceinline__ void cp_commit(){ asm volatile("cp.async.commit_group;"); }
template<int N> __device__ __forceinline__ void cp_wait(){
    asm volatile("cp.async.wait_group %0;" :: "n"(N));
}

// ---------------- phase 0: boundary reductions ----------------
__global__ void rows_kernel(const float* __restrict__ hid,
                            const float* __restrict__ cel,
                            const float* __restrict__ gts)
{
    int gid = blockIdx.x*256 + threadIdx.x;        // over NB*B*H
    int j = gid / (B_*H);
    int rem = gid - j*(B_*H);
    int b = rem >> 7, h = rem & 127;
    const float* ph = hid + (b*TIN*NB + j)*H + h;
    const float* pc = cel + (b*TIN*NB + j)*H + h;
    float sh = 0.f, sc = 0.f;
    for (int t = 0; t < TIN; ++t) { sh += ph[t*NB*H]; sc += pc[t*NB*H]; }
    int o = (j*B_ + b)*H + h;
    g_row_h0[o] = sh * (1.0f/TIN);
    g_row_h1[o] = (gts[(b*NB + j)*H + h] + sh) * (1.0f/(TIN+1));
    g_row_c [o] = sc * (1.0f/TIN);
}

__global__ void cols_kernel()
{
    int gid = blockIdx.x*256 + threadIdx.x;        // over B*H
    float sh = 0.f, sc = 0.f;
#pragma unroll
    for (int j = 0; j < NB; ++j) {
        sh += g_row_h0[j*B_*H + gid];
        sc += g_row_c [j*B_*H + gid];
    }
    g_col_h[gid] = sh * (1.0f/NB);
    g_col_c[gid] = sc * (1.0f/NB);
}

// ------- fp32 GEMM core: 64x128 tile, 128 thr, 8x8/thread, K=128 -------
// A fully staged [k][m]; B 4-stage cp.async ring. Conflict-free split mapping.
__device__ __forceinline__ void gemm_src(const float* __restrict__ A, int lda,
                                         const float* __restrict__ W,
                                         float* __restrict__ Cbase,
                                         const float* __restrict__ bias)
{
    __shared__ float sA[128][64];          // [k][m]  32 KB
    __shared__ float sB[4][8][128];        // 4-stage ring, BK=8  16 KB

    const int tid = threadIdx.x;
    const int m0 = (blockIdx.x & 3) * 64;      // 4 m-tiles of 64
    const int n0 = (blockIdx.x >> 2) * 128;    // 5 n-tiles of 128

    // A staging map: 64 rows x 128 k, 128 threads -> 16 float4 each
    const int am = tid >> 1;             // 0..63
    const int ak = (tid & 1) * 4;        // 0 or 4; k = ak + 8*pos
    // B cp.async map: per chunk 8x128 floats, 2 cp16 per thread
    const int bk = tid >> 4;             // 0..7
    const int bn = (tid & 15) * 8;       // 0..120

    // compute map: 8x16 thread grid, split 4+4 in m and n
    const int trow = tid >> 4;           // 0..7
    const int tcol = tid & 15;           // 0..15
    const int m_lo = trow * 4;           // 0..28
    const int m_hi = 32 + trow * 4;      // 32..60
    const int n_lo = tcol * 4;           // 0..60
    const int n_hi = 64 + tcol * 4;      // 64..124

    const float* Arow  = A + (m0 + am)*lda + ak;
    const float* Bbase = W + bk*G5 + n0 + bn;
    uint32_t sb0 = (uint32_t)__cvta_generic_to_shared(&sB[0][bk][bn]);

    // ---- prologue: issue B chunks 0..2, stage all of A ----
#pragma unroll
    for (int ch = 0; ch < 3; ++ch) {
        cp16(sb0 + (uint32_t)(ch*8*128*4),      Bbase + ch*8*G5);
        cp16(sb0 + (uint32_t)(ch*8*128*4) + 16, Bbase + ch*8*G5 + 4);
        cp_commit();
    }
#pragma unroll
    for (int pos = 0; pos < 16; ++pos) {
        float4 v = *(const float4*)(Arow + pos*8);
        sA[ak + pos*8 + 0][am] = v.x;
        sA[ak + pos*8 + 1][am] = v.y;
        sA[ak + pos*8 + 2][am] = v.z;
        sA[ak + pos*8 + 3][am] = v.w;
    }

    u64 acc[8][4];
#pragma unroll
    for (int i = 0; i < 8; ++i)
#pragma unroll
        for (int jj = 0; jj < 4; ++jj) acc[i][jj] = 0ull;

    // ---- mainloop: 16 chunks of BK=8 ----
#pragma unroll
    for (int c = 0; c < 16; ++c) {
        if (c <= 13) cp_wait<2>(); else if (c == 14) cp_wait<1>(); else cp_wait<0>();
        __syncthreads();
        if (c + 3 < 16) {
            cp16(sb0 + (uint32_t)(((c+3)&3)*8*128*4),      Bbase + (c+3)*8*G5);
            cp16(sb0 + (uint32_t)(((c+3)&3)*8*128*4) + 16, Bbase + (c+3)*8*G5 + 4);
            cp_commit();
        }
        const int st = c & 3;
#pragma unroll
        for (int k = 0; k < 8; ++k) {
            float4 a0 = *(const float4*)&sA[c*8 + k][m_lo];   // broadcast in warp
            float4 a1 = *(const float4*)&sA[c*8 + k][m_hi];
            ulonglong2 q0 = *(const ulonglong2*)&sB[st][k][n_lo];  // contiguous 16B/lane
            ulonglong2 q1 = *(const ulonglong2*)&sB[st][k][n_hi];
            float av[8] = {a0.x, a0.y, a0.z, a0.w, a1.x, a1.y, a1.z, a1.w};
#pragma unroll
            for (int i = 0; i < 8; ++i) {
                u64 ad = pack2(av[i], av[i]);
                acc[i][0] = ffma2(ad, q0.x, acc[i][0]);
                acc[i][1] = ffma2(ad, q0.y, acc[i][1]);
                acc[i][2] = ffma2(ad, q1.x, acc[i][2]);
                acc[i][3] = ffma2(ad, q1.y, acc[i][3]);
            }
        }
    }

    // ---- epilogue: 2 STG.128 per owned row ----
#pragma unroll
    for (int i = 0; i < 8; ++i) {
        const int m = m0 + ((i < 4) ? (m_lo + i) : (m_hi + i - 4));
        float* Crow = Cbase + (long)m*G5 + n0;
        float x0, x1, x2, x3;
        unpack2(acc[i][0], x0, x1);
        unpack2(acc[i][1], x2, x3);
        if (bias) {
            float4 bb = *(const float4*)(bias + n0 + n_lo);
            x0 += bb.x; x1 += bb.y; x2 += bb.z; x3 += bb.w;
        }
        float4 v0; v0.x = x0; v0.y = x1; v0.z = x2; v0.w = x3;
        *(float4*)(Crow + n_lo) = v0;
        unpack2(acc[i][2], x0, x1);
        unpack2(acc[i][3], x2, x3);
        if (bias) {
            float4 bb = *(const float4*)(bias + n0 + n_hi);
            x0 += bb.x; x1 += bb.y; x2 += bb.z; x3 += bb.w;
        }
        float4 v1; v1.x = x0; v1.y = x1; v1.z = x2; v1.w = x3;
        *(float4*)(Crow + n_hi) = v1;
    }
}

// ---------------- phase 1: xU0 = p @ U[0] + b[0] ----------------
__global__ __launch_bounds__(128, 4) void gemm_xu0_kernel(const float* __restrict__ p,
                                                          const float* __restrict__ U,
                                                          const float* __restrict__ bvec)
{
    int cell = blockIdx.y;
    int t = cell / NB, j = cell - t*NB;
    gemm_src(p + (t*NB + j)*H, OSTRIDE, U + j*H*G5,
             g_xu0 + (long)cell*B_*G5, bvec + j*G5);
}

// ---------------- phase 2: wavefront steps (d = t + j (+1 for rec1)) ----------------
struct StepList { int n; int cells[64]; };

__global__ __launch_bounds__(128, 4) void gemm_step_kernel(StepList sl,
                                                           const float* __restrict__ U,
                                                           const float* __restrict__ Wt,
                                                           const float* __restrict__ Ws,
                                                           const float* __restrict__ bvec,
                                                           const float* __restrict__ outH)
{
    int code = sl.cells[blockIdx.y];
    int r = code >> 16, t = (code >> 8) & 255, j = code & 255;
    int src = blockIdx.z;
    const float* A; int lda; const float* W; const float* bias = nullptr;
    if (r == 0) {
        if (src == 2) return;                  // rec-0 has only 2 recurrent sources
        if (src == 0) {
            A = (t == 0) ? g_row_h0 + j*B_*H : g_h0 + ((t-1)*NB + j)*B_*H;
            lda = H;  W = Wt + j*H*G5;
        } else {
            A = (j == 0) ? g_col_h : g_h0 + (t*NB + (j-1))*B_*H;
            lda = H;  W = Ws + j*H*G5;
        }
    } else {
        if (src == 0) {
            A = g_h0 + (t*NB + j)*B_*H;  lda = H;  W = U + (NB + j)*H*G5;
            bias = bvec + (NB + j)*G5;
        } else if (src == 1) {
            if (t == 0) { A = g_row_h1 + j*B_*H;        lda = H; }
            else        { A = outH + ((t-1)*NB + j)*H;  lda = OSTRIDE; }
            W = Wt + (NB + j)*H*G5;
        } else {
            if (j == 0) { A = g_col_h;                  lda = H; }
            else        { A = outH + (t*NB + (j-1))*H;  lda = OSTRIDE; }
            W = Ws + (NB + j)*H*G5;
        }
    }
    gemm_src(A, lda, W, g_z + ((long)blockIdx.y*3 + src)*B_*G5, bias);
}

__device__ __forceinline__ float sigf(float x){ return 1.0f/(1.0f + __expf(-x)); }
__device__ __forceinline__ float tanhfast(float x){ return 2.0f*sigf(2.0f*x) - 1.0f; }

__global__ __launch_bounds__(256) void ew_step_kernel(StepList sl,
                                                      float* __restrict__ outH)
{
    int code = sl.cells[blockIdx.y];
    int r = code >> 16, t = (code >> 8) & 255, j = code & 255;
    int e = blockIdx.x*256 + threadIdx.x;      // 0..B*H-1
    int m = e >> 7, h = e & 127;
    const float* zb = g_z + (long)blockIdx.y*3*B_*G5 + m*G5 + h;
    const float* z1p = zb + (long)B_*G5;
    const float* z2p = zb + (long)2*B_*G5;
    float z0 = zb[0]   + z1p[0];
    float z1 = zb[128] + z1p[128];
    float z2 = zb[256] + z1p[256];
    float z3 = zb[384] + z1p[384];
    float z4 = zb[512] + z1p[512];
    float ct, cs;
    float* outC = outH + (long)B_*TOUT*NB*H;
    if (r == 0) {
        const float* xb = g_xu0 + ((long)(t*NB + j)*B_ + m)*G5 + h;
        z0 += xb[0]; z1 += xb[128]; z2 += xb[256]; z3 += xb[384]; z4 += xb[512];
        ct = (t == 0) ? g_row_c[(j*B_ + m)*H + h]
                      : g_c0[(((t-1)*NB + j)*B_ + m)*H + h];
        cs = (j == 0) ? g_col_c[m*H + h]
                      : g_c0[((t*NB + (j-1))*B_ + m)*H + h];
    } else {
        z0 += z2p[0]; z1 += z2p[128]; z2 += z2p[256]; z3 += z2p[384]; z4 += z2p[512];
        ct = (t == 0) ? g_row_c[(j*B_ + m)*H + h]
                      : outC[((m*TOUT + (t-1))*NB + j)*H + h];
        cs = (j == 0) ? g_col_c[m*H + h]
                      : outC[((m*TOUT + t)*NB + (j-1))*H + h];
    }
    // gate order: i, f_s, f_t, o, g
    float in_ = sigf(z0), fs = sigf(z1), ft = sigf(z2), o = sigf(z3), g = tanhfast(z4);
    float c  = in_*g + ft*ct + fs*cs;
    float hv = o * tanhfast(c);
    if (r == 0) {
        int idx = ((t*NB + j)*B_ + m)*H + h;
        g_h0[idx] = hv;  g_c0[idx] = c;
    } else {
        int idx = ((m*TOUT + t)*NB + j)*H + h;
        outH[idx] = hv;  outC[idx] = c;
    }
}

// ---------------- launch ----------------
extern "C" void kernel_launch(void* const* d_in, const int* in_sizes, int n_in,
                              void* d_out, int out_size)
{
    const float* hid = (const float*)d_in[0];
    const float* cel = (const float*)d_in[1];
    const float* gts = (const float*)d_in[2];
    const float* p   = (const float*)d_in[3];
    const float* U   = (const float*)d_in[4];
    const float* Wt  = (const float*)d_in[5];
    const float* Ws  = (const float*)d_in[6];
    const float* bv  = (const float*)d_in[7];
    float* outH = (float*)d_out;

    rows_kernel<<<NB*B_*H/256, 256>>>(hid, cel, gts);
    cols_kernel<<<B_*H/256, 256>>>();
    gemm_xu0_kernel<<<dim3(20, TOUT*NB), 128>>>(p, U, bv);

    // wavefront: rec0 at d = t+j, rec1 at d = t+j+1, d in [0, 48]
    for (int d = 0; d <= (TOUT-1) + (NB-1) + 1; ++d) {
        StepList sl; sl.n = 0;
        for (int t = 0; t < TOUT; ++t) {               // rec 0: t + j = d
            int j = d - t;
            if (j >= 0 && j < NB) sl.cells[sl.n++] = (0 << 16) | (t << 8) | j;
        }
        for (int t = 0; t < TOUT; ++t) {               // rec 1: t + j = d - 1
            int j = d - 1 - t;
            if (j >= 0 && j < NB) sl.cells[sl.n++] = (1 << 16) | (t << 8) | j;
        }
        if (!sl.n) continue;
        gemm_step_kernel<<<dim3(20, sl.n, 3), 128>>>(sl, U, Wt, Ws, bv, outH);
        ew_step_kernel<<<dim3(B_*H/256, sl.n), 256>>>(sl, outH);
    }
}